// round 1
// baseline (speedup 1.0000x reference)
#include <cuda_runtime.h>
#include <cuda_bf16.h>
#include <math.h>

#define Bq 4
#define Sq 1024
#define Dq 768
#define Hq 12
#define HDq 64
#define FFq 3072
#define Mq (Bq*Sq)   // 4096
#define EPSq 1e-5f

// ---------------- scratch (static device globals; no allocation) ----------------
__device__ float g_h [Mq*Dq];
__device__ float g_q [Mq*Dq];
__device__ float g_k [Mq*Dq];
__device__ float g_v [Mq*Dq];
__device__ float g_at[Mq*Dq];
__device__ float g_x2[Mq*Dq];
__device__ float g_ff[Mq*FFq];

// ---------------- LayerNorm: one block per row, D=768 ----------------
__global__ void ln_kernel(const float* __restrict__ x,
                          const float* __restrict__ g,
                          const float* __restrict__ s,
                          float* __restrict__ out) {
    int row = blockIdx.x;
    int t = threadIdx.x;            // 256 threads, 3 elems each
    const float* xr = x + (size_t)row * Dq;
    float v0 = xr[t], v1 = xr[t + 256], v2 = xr[t + 512];
    float lsum = v0 + v1 + v2;
    float lsq  = v0*v0 + v1*v1 + v2*v2;

    __shared__ float rs[64], rq[64];
    // warp reduce
    for (int o = 16; o > 0; o >>= 1) {
        lsum += __shfl_down_sync(0xffffffff, lsum, o);
        lsq  += __shfl_down_sync(0xffffffff, lsq,  o);
    }
    int warp = t >> 5, lane = t & 31;
    if (lane == 0) { rs[warp] = lsum; rq[warp] = lsq; }
    __syncthreads();
    if (warp == 0) {
        float a = (lane < 8) ? rs[lane] : 0.f;
        float b = (lane < 8) ? rq[lane] : 0.f;
        for (int o = 4; o > 0; o >>= 1) {
            a += __shfl_down_sync(0xffffffff, a, o);
            b += __shfl_down_sync(0xffffffff, b, o);
        }
        if (lane == 0) { rs[0] = a; rq[0] = b; }
    }
    __syncthreads();
    float mean = rs[0] * (1.0f / Dq);
    float var  = rq[0] * (1.0f / Dq) - mean * mean;
    float inv  = rsqrtf(var + EPSq);
    float* orow = out + (size_t)row * Dq;
    orow[t]       = (v0 - mean) * inv * g[t]       + s[t];
    orow[t + 256] = (v1 - mean) * inv * g[t + 256] + s[t + 256];
    orow[t + 512] = (v2 - mean) * inv * g[t + 512] + s[t + 512];
}

// ---------------- SGEMM: C[M,N] = A[M,K] @ W[N,K]^T (+bias)(+gelu)(+res) ----------------
// BM=BN=64, BK=16, 256 threads, 4x4 microtile per thread.
template<bool HAS_BIAS, bool DO_GELU, bool HAS_RES>
__global__ void sgemm_kernel(const float* __restrict__ A,
                             const float* __restrict__ W,
                             const float* __restrict__ bias,
                             const float* __restrict__ res,
                             float* __restrict__ C,
                             int M, int N, int K) {
    __shared__ float As[16][64];
    __shared__ float Bs[16][64];

    int tid = threadIdx.x;
    int bm = blockIdx.y, bn = blockIdx.x;

    int lrow = tid >> 2;          // 0..63
    int kc   = (tid & 3) * 4;     // 0,4,8,12

    const float* Ap = A + (size_t)(bm * 64 + lrow) * K + kc;
    const float* Wp = W + (size_t)(bn * 64 + lrow) * K + kc;

    int ty = tid >> 4, tx = tid & 15;
    float c[4][4];
    #pragma unroll
    for (int i = 0; i < 4; i++)
        #pragma unroll
        for (int j = 0; j < 4; j++) c[i][j] = 0.f;

    for (int k0 = 0; k0 < K; k0 += 16) {
        float4 a = *(const float4*)(Ap + k0);
        float4 w = *(const float4*)(Wp + k0);
        As[kc + 0][lrow] = a.x; As[kc + 1][lrow] = a.y;
        As[kc + 2][lrow] = a.z; As[kc + 3][lrow] = a.w;
        Bs[kc + 0][lrow] = w.x; Bs[kc + 1][lrow] = w.y;
        Bs[kc + 2][lrow] = w.z; Bs[kc + 3][lrow] = w.w;
        __syncthreads();
        #pragma unroll
        for (int kk = 0; kk < 16; kk++) {
            float4 av = *(const float4*)&As[kk][ty * 4];
            float4 bv = *(const float4*)&Bs[kk][tx * 4];
            float ar[4] = {av.x, av.y, av.z, av.w};
            float br[4] = {bv.x, bv.y, bv.z, bv.w};
            #pragma unroll
            for (int i = 0; i < 4; i++)
                #pragma unroll
                for (int j = 0; j < 4; j++)
                    c[i][j] += ar[i] * br[j];
        }
        __syncthreads();
    }

    #pragma unroll
    for (int i = 0; i < 4; i++) {
        int m = bm * 64 + ty * 4 + i;
        #pragma unroll
        for (int j = 0; j < 4; j++) {
            int n = bn * 64 + tx * 4 + j;
            float v = c[i][j];
            if (HAS_BIAS) v += bias[n];
            if (DO_GELU) {
                float x3 = v * v * v;
                float tt = tanhf(0.7978845608028654f * (v + 0.044715f * x3));
                v = 0.5f * v * (1.0f + tt);
            }
            if (HAS_RES) v += res[(size_t)m * N + n];
            C[(size_t)m * N + n] = v;
        }
    }
}

// ---------------- Attention: one block per (b,h,q) — view-space contiguous slices ----------------
__global__ void attn_kernel(const float* __restrict__ Q,
                            const float* __restrict__ K,
                            const float* __restrict__ V,
                            float* __restrict__ out) {
    int idx = blockIdx.x;               // b*H*S + h*S + q
    int q  = idx & (Sq - 1);
    int bh = idx >> 10;                 // b*H + h
    int h  = bh % Hq;
    int b  = bh / Hq;

    const float* Qp = Q + (size_t)bh * Sq * HDq;
    const float* Kp = K + (size_t)bh * Sq * HDq;
    const float* Vp = V + (size_t)bh * Sq * HDq;

    __shared__ float qs[HDq];
    __shared__ float sc[Sq];
    __shared__ float red[128];

    int t = threadIdx.x;                // 128 threads
    if (t < HDq) qs[t] = Qp[q * HDq + t];
    __syncthreads();

    int nk = q + 1;
    float lmax = -1e30f;
    for (int k = t; k < nk; k += 128) {
        const float* Kr = Kp + k * HDq;
        float dot = 0.f;
        #pragma unroll
        for (int d = 0; d < HDq; d++) dot += qs[d] * Kr[d];
        dot *= (1.0f / HDq);
        sc[k] = dot;
        lmax = fmaxf(lmax, dot);
    }
    red[t] = lmax;
    __syncthreads();
    for (int o = 64; o > 0; o >>= 1) {
        if (t < o) red[t] = fmaxf(red[t], red[t + o]);
        __syncthreads();
    }
    float mx = red[0];
    __syncthreads();

    float lsum = 0.f;
    for (int k = t; k < nk; k += 128) {
        float e = __expf(sc[k] - mx);
        sc[k] = e;
        lsum += e;
    }
    red[t] = lsum;
    __syncthreads();
    for (int o = 64; o > 0; o >>= 1) {
        if (t < o) red[t] += red[t + o];
        __syncthreads();
    }
    float inv = 1.0f / red[0];
    __syncthreads();

    // A @ V : 2 partitions over k, 64 dims
    int d = t & 63, part = t >> 6;
    float acc = 0.f;
    for (int k = part; k < nk; k += 2)
        acc += sc[k] * Vp[k * HDq + d];
    red[t] = acc;
    __syncthreads();
    if (t < HDq) {
        float r = (red[t] + red[t + 64]) * inv;
        // out[b, q, h*HD + d]  (swapaxes(1,2).reshape)
        out[((size_t)(b * Sq + q)) * Dq + h * HDq + t] = r;
    }
}

// ---------------- launch ----------------
extern "C" void kernel_launch(void* const* d_in, const int* in_sizes, int n_in,
                              void* d_out, int out_size) {
    const float* x  = (const float*)d_in[0];
    const float* Wq = (const float*)d_in[1];
    const float* Wk = (const float*)d_in[2];
    const float* Wv = (const float*)d_in[3];
    const float* Wo = (const float*)d_in[4];
    const float* W1 = (const float*)d_in[5];
    const float* b1 = (const float*)d_in[6];
    const float* W2 = (const float*)d_in[7];
    const float* b2 = (const float*)d_in[8];
    const float* g1 = (const float*)d_in[9];
    const float* s1 = (const float*)d_in[10];
    const float* g2 = (const float*)d_in[11];
    const float* s2 = (const float*)d_in[12];
    float* out = (float*)d_out;

    float *h, *q, *k, *v, *at, *x2, *ff;
    cudaGetSymbolAddress((void**)&h,  g_h);
    cudaGetSymbolAddress((void**)&q,  g_q);
    cudaGetSymbolAddress((void**)&k,  g_k);
    cudaGetSymbolAddress((void**)&v,  g_v);
    cudaGetSymbolAddress((void**)&at, g_at);
    cudaGetSymbolAddress((void**)&x2, g_x2);
    cudaGetSymbolAddress((void**)&ff, g_ff);

    dim3 gDD(Dq / 64, Mq / 64);     // (12, 64)
    dim3 gDF(FFq / 64, Mq / 64);    // (48, 64)

    // LN1
    ln_kernel<<<Mq, 256>>>(x, g1, s1, h);
    // Q, K, V projections
    sgemm_kernel<false, false, false><<<gDD, 256>>>(h, Wq, nullptr, nullptr, q, Mq, Dq, Dq);
    sgemm_kernel<false, false, false><<<gDD, 256>>>(h, Wk, nullptr, nullptr, k, Mq, Dq, Dq);
    sgemm_kernel<false, false, false><<<gDD, 256>>>(h, Wv, nullptr, nullptr, v, Mq, Dq, Dq);
    // attention
    attn_kernel<<<Bq * Hq * Sq, 128>>>(q, k, v, at);
    // output projection + residual
    sgemm_kernel<false, false, true><<<gDD, 256>>>(at, Wo, nullptr, x, x2, Mq, Dq, Dq);
    // LN2
    ln_kernel<<<Mq, 256>>>(x2, g2, s2, h);
    // MLP up + GELU
    sgemm_kernel<true, true, false><<<gDF, 256>>>(h, W1, b1, nullptr, ff, Mq, FFq, Dq);
    // MLP down + bias + residual -> out
    sgemm_kernel<true, false, true><<<gDD, 256>>>(ff, W2, b2, x2, out, Mq, Dq, FFq);
}

// round 2
// speedup vs baseline: 4.0658x; 4.0658x over previous
#include <cuda_runtime.h>
#include <cuda_bf16.h>
#include <math.h>

#define Bq 4
#define Sq 1024
#define Dq 768
#define Hq 12
#define HDq 64
#define FFq 3072
#define Mq (Bq*Sq)   // 4096
#define EPSq 1e-5f

// ---------------- scratch (static device globals; no allocation) ----------------
__device__ float g_h [Mq*Dq];
__device__ float g_q [Mq*Dq];
__device__ float g_k [Mq*Dq];
__device__ float g_v [Mq*Dq];
__device__ float g_at[Mq*Dq];
__device__ float g_x2[Mq*Dq];
__device__ float g_ff[Mq*FFq];

// ---------------- LayerNorm: one block per row, D=768 ----------------
__global__ void ln_kernel(const float* __restrict__ x,
                          const float* __restrict__ g,
                          const float* __restrict__ s,
                          float* __restrict__ out) {
    int row = blockIdx.x;
    int t = threadIdx.x;            // 256 threads, 3 elems each
    const float* xr = x + (size_t)row * Dq;
    float v0 = xr[t], v1 = xr[t + 256], v2 = xr[t + 512];
    float lsum = v0 + v1 + v2;
    float lsq  = v0*v0 + v1*v1 + v2*v2;

    __shared__ float rs[64], rq[64];
    for (int o = 16; o > 0; o >>= 1) {
        lsum += __shfl_down_sync(0xffffffff, lsum, o);
        lsq  += __shfl_down_sync(0xffffffff, lsq,  o);
    }
    int warp = t >> 5, lane = t & 31;
    if (lane == 0) { rs[warp] = lsum; rq[warp] = lsq; }
    __syncthreads();
    if (warp == 0) {
        float a = (lane < 8) ? rs[lane] : 0.f;
        float b = (lane < 8) ? rq[lane] : 0.f;
        for (int o = 4; o > 0; o >>= 1) {
            a += __shfl_down_sync(0xffffffff, a, o);
            b += __shfl_down_sync(0xffffffff, b, o);
        }
        if (lane == 0) { rs[0] = a; rq[0] = b; }
    }
    __syncthreads();
    float mean = rs[0] * (1.0f / Dq);
    float var  = rq[0] * (1.0f / Dq) - mean * mean;
    float inv  = rsqrtf(var + EPSq);
    float* orow = out + (size_t)row * Dq;
    orow[t]       = (v0 - mean) * inv * g[t]       + s[t];
    orow[t + 256] = (v1 - mean) * inv * g[t + 256] + s[t + 256];
    orow[t + 512] = (v2 - mean) * inv * g[t + 512] + s[t + 512];
}

// ---------------- SGEMM: C[M,N] = A[M,K] @ W[N,K]^T (+bias)(+gelu)(+res) ----------------
// BM=128, BN=64, BK=16, 256 threads, 8x4 microtile per thread.
template<bool HAS_BIAS, bool DO_GELU, bool HAS_RES>
__global__ void sgemm_kernel(const float* __restrict__ A,
                             const float* __restrict__ W,
                             const float* __restrict__ bias,
                             const float* __restrict__ res,
                             float* __restrict__ C,
                             int M, int N, int K) {
    __shared__ float As[16][128];
    __shared__ float Bs[16][68];

    int tid = threadIdx.x;
    int bm = blockIdx.y, bn = blockIdx.x;

    int lrA = tid >> 1;           // 0..127
    int kcA = (tid & 1) * 8;      // 0 or 8
    int lrB = tid >> 2;           // 0..63
    int kcB = (tid & 3) * 4;      // 0,4,8,12

    const float* Ap = A + (size_t)(bm * 128 + lrA) * K + kcA;
    const float* Wp = W + (size_t)(bn * 64  + lrB) * K + kcB;

    int ty = tid >> 4, tx = tid & 15;   // ty: 0..15 (8 rows each), tx: 0..15 (4 cols each)
    float c[8][4];
    #pragma unroll
    for (int i = 0; i < 8; i++)
        #pragma unroll
        for (int j = 0; j < 4; j++) c[i][j] = 0.f;

    for (int k0 = 0; k0 < K; k0 += 16) {
        float4 a0 = *(const float4*)(Ap + k0);
        float4 a1 = *(const float4*)(Ap + k0 + 4);
        float4 w  = *(const float4*)(Wp + k0);
        As[kcA + 0][lrA] = a0.x; As[kcA + 1][lrA] = a0.y;
        As[kcA + 2][lrA] = a0.z; As[kcA + 3][lrA] = a0.w;
        As[kcA + 4][lrA] = a1.x; As[kcA + 5][lrA] = a1.y;
        As[kcA + 6][lrA] = a1.z; As[kcA + 7][lrA] = a1.w;
        Bs[kcB + 0][lrB] = w.x;  Bs[kcB + 1][lrB] = w.y;
        Bs[kcB + 2][lrB] = w.z;  Bs[kcB + 3][lrB] = w.w;
        __syncthreads();
        #pragma unroll
        for (int kk = 0; kk < 16; kk++) {
            float4 x0 = *(const float4*)&As[kk][ty * 8];
            float4 x1 = *(const float4*)&As[kk][ty * 8 + 4];
            float4 bv = *(const float4*)&Bs[kk][tx * 4];
            float ar[8] = {x0.x, x0.y, x0.z, x0.w, x1.x, x1.y, x1.z, x1.w};
            float br[4] = {bv.x, bv.y, bv.z, bv.w};
            #pragma unroll
            for (int i = 0; i < 8; i++)
                #pragma unroll
                for (int j = 0; j < 4; j++)
                    c[i][j] += ar[i] * br[j];
        }
        __syncthreads();
    }

    #pragma unroll
    for (int i = 0; i < 8; i++) {
        int m = bm * 128 + ty * 8 + i;
        #pragma unroll
        for (int j = 0; j < 4; j++) {
            int n = bn * 64 + tx * 4 + j;
            float v = c[i][j];
            if (HAS_BIAS) v += bias[n];
            if (DO_GELU) {
                float x3 = v * v * v;
                float tt = tanhf(0.7978845608028654f * (v + 0.044715f * x3));
                v = 0.5f * v * (1.0f + tt);
            }
            if (HAS_RES) v += res[(size_t)m * N + n];
            C[(size_t)m * N + n] = v;
        }
    }
}

// ---------------- Flash attention: block = (b,h) x 64-row q tile ----------------
// SMEM buffers stride 68 floats (conflict-free patterns), dynamic smem 69632B.
#define ATS 68
#define AT_SMEM_BYTES (4 * 64 * ATS * 4)

__global__ void attn_kernel(const float* __restrict__ Q,
                            const float* __restrict__ K,
                            const float* __restrict__ V,
                            float* __restrict__ out) {
    extern __shared__ float sm[];
    float* Qs = sm;                 // [64][ATS]  (row, d), pre-scaled by 1/64
    float* KT = sm + 64 * ATS;      // [64][ATS]  (d, k)
    float* Vs = sm + 2 * 64 * ATS;  // [64][ATS]  (k, d)
    float* Ps = sm + 3 * 64 * ATS;  // [64][ATS]  (row, k)

    int bh = blockIdx.y;            // b*H + h
    int qt = 15 - blockIdx.x;       // heavy tiles first
    int tid = threadIdx.x;          // 256
    int tx = tid & 15, ty = tid >> 4;

    const float* Qp = Q + (size_t)bh * Sq * HDq;
    const float* Kp = K + (size_t)bh * Sq * HDq;
    const float* Vp = V + (size_t)bh * Sq * HDq;

    // load Q tile, scaled by 1/HD (scores = QK^T / 64 folded here)
    for (int t = tid; t < 64 * 16; t += 256) {
        int r = t >> 4, c = (t & 15) * 4;
        float4 qv = *(const float4*)(Qp + (size_t)(qt * 64 + r) * HDq + c);
        qv.x *= (1.0f / 64.0f); qv.y *= (1.0f / 64.0f);
        qv.z *= (1.0f / 64.0f); qv.w *= (1.0f / 64.0f);
        *(float4*)(Qs + r * ATS + c) = qv;
    }

    float o[4][4];
    float m_i[4], l_i[4];
    #pragma unroll
    for (int i = 0; i < 4; i++) {
        m_i[i] = -1e30f; l_i[i] = 0.f;
        #pragma unroll
        for (int j = 0; j < 4; j++) o[i][j] = 0.f;
    }

    for (int kt = 0; kt <= qt; kt++) {
        __syncthreads();   // protect prior-iter KT/Vs/Ps reads (and Qs before first use)
        // load K (transposed to KT[d][k]) and V (natural Vs[k][d])
        for (int t = tid; t < 1024; t += 256) {
            int k = t & 63, c = (t >> 6) * 4;   // c = 0,4,..,60
            float4 kv = *(const float4*)(Kp + (size_t)(kt * 64 + k) * HDq + c);
            KT[(c + 0) * ATS + k] = kv.x;
            KT[(c + 1) * ATS + k] = kv.y;
            KT[(c + 2) * ATS + k] = kv.z;
            KT[(c + 3) * ATS + k] = kv.w;
            float4 vv = *(const float4*)(Vp + (size_t)(kt * 64 + k) * HDq + c);
            *(float4*)(Vs + k * ATS + c) = vv;
        }
        __syncthreads();

        // S = Q @ K^T (pre-scaled)
        float s[4][4];
        #pragma unroll
        for (int i = 0; i < 4; i++)
            #pragma unroll
            for (int j = 0; j < 4; j++) s[i][j] = 0.f;
        #pragma unroll 4
        for (int d = 0; d < 64; d++) {
            float4 kv = *(const float4*)(KT + d * ATS + tx * 4);
            float q0 = Qs[(ty * 4 + 0) * ATS + d];
            float q1 = Qs[(ty * 4 + 1) * ATS + d];
            float q2 = Qs[(ty * 4 + 2) * ATS + d];
            float q3 = Qs[(ty * 4 + 3) * ATS + d];
            s[0][0] += q0 * kv.x; s[0][1] += q0 * kv.y; s[0][2] += q0 * kv.z; s[0][3] += q0 * kv.w;
            s[1][0] += q1 * kv.x; s[1][1] += q1 * kv.y; s[1][2] += q1 * kv.z; s[1][3] += q1 * kv.w;
            s[2][0] += q2 * kv.x; s[2][1] += q2 * kv.y; s[2][2] += q2 * kv.z; s[2][3] += q2 * kv.w;
            s[3][0] += q3 * kv.x; s[3][1] += q3 * kv.y; s[3][2] += q3 * kv.z; s[3][3] += q3 * kv.w;
        }

        // causal mask on diagonal tile
        if (kt == qt) {
            #pragma unroll
            for (int i = 0; i < 4; i++)
                #pragma unroll
                for (int j = 0; j < 4; j++)
                    if (tx * 4 + j > ty * 4 + i) s[i][j] = -1e30f;
        }

        // online softmax update (row groups = 16 lanes sharing ty)
        #pragma unroll
        for (int i = 0; i < 4; i++) {
            float mx = fmaxf(fmaxf(s[i][0], s[i][1]), fmaxf(s[i][2], s[i][3]));
            #pragma unroll
            for (int off = 1; off < 16; off <<= 1)
                mx = fmaxf(mx, __shfl_xor_sync(0xffffffff, mx, off));
            float Mnew = fmaxf(m_i[i], mx);
            float alpha = __expf(m_i[i] - Mnew);
            float rs = 0.f;
            #pragma unroll
            for (int j = 0; j < 4; j++) {
                float e = __expf(s[i][j] - Mnew);
                s[i][j] = e;
                rs += e;
            }
            #pragma unroll
            for (int off = 1; off < 16; off <<= 1)
                rs += __shfl_xor_sync(0xffffffff, rs, off);
            l_i[i] = l_i[i] * alpha + rs;
            m_i[i] = Mnew;
            #pragma unroll
            for (int j = 0; j < 4; j++) o[i][j] *= alpha;
        }

        // stage P
        #pragma unroll
        for (int i = 0; i < 4; i++)
            *(float4*)(Ps + (ty * 4 + i) * ATS + tx * 4) =
                make_float4(s[i][0], s[i][1], s[i][2], s[i][3]);
        __syncthreads();

        // O += P @ V
        #pragma unroll 4
        for (int k = 0; k < 64; k++) {
            float4 vv = *(const float4*)(Vs + k * ATS + tx * 4);
            float p0 = Ps[(ty * 4 + 0) * ATS + k];
            float p1 = Ps[(ty * 4 + 1) * ATS + k];
            float p2 = Ps[(ty * 4 + 2) * ATS + k];
            float p3 = Ps[(ty * 4 + 3) * ATS + k];
            o[0][0] += p0 * vv.x; o[0][1] += p0 * vv.y; o[0][2] += p0 * vv.z; o[0][3] += p0 * vv.w;
            o[1][0] += p1 * vv.x; o[1][1] += p1 * vv.y; o[1][2] += p1 * vv.z; o[1][3] += p1 * vv.w;
            o[2][0] += p2 * vv.x; o[2][1] += p2 * vv.y; o[2][2] += p2 * vv.z; o[2][3] += p2 * vv.w;
            o[3][0] += p3 * vv.x; o[3][1] += p3 * vv.y; o[3][2] += p3 * vv.z; o[3][3] += p3 * vv.w;
        }
    }

    // epilogue: normalize and scatter to (b, q, h*64+d)
    int b = bh / Hq, h = bh % Hq;
    #pragma unroll
    for (int i = 0; i < 4; i++) {
        float inv = 1.0f / l_i[i];
        int qrow = qt * 64 + ty * 4 + i;
        float* orow = out + ((size_t)(b * Sq + qrow)) * Dq + h * HDq + tx * 4;
        float4 r = make_float4(o[i][0] * inv, o[i][1] * inv, o[i][2] * inv, o[i][3] * inv);
        *(float4*)orow = r;
    }
}

// ---------------- launch ----------------
extern "C" void kernel_launch(void* const* d_in, const int* in_sizes, int n_in,
                              void* d_out, int out_size) {
    const float* x  = (const float*)d_in[0];
    const float* Wq = (const float*)d_in[1];
    const float* Wk = (const float*)d_in[2];
    const float* Wv = (const float*)d_in[3];
    const float* Wo = (const float*)d_in[4];
    const float* W1 = (const float*)d_in[5];
    const float* b1 = (const float*)d_in[6];
    const float* W2 = (const float*)d_in[7];
    const float* b2 = (const float*)d_in[8];
    const float* g1 = (const float*)d_in[9];
    const float* s1 = (const float*)d_in[10];
    const float* g2 = (const float*)d_in[11];
    const float* s2 = (const float*)d_in[12];
    float* out = (float*)d_out;

    float *h, *q, *k, *v, *at, *x2, *ff;
    cudaGetSymbolAddress((void**)&h,  g_h);
    cudaGetSymbolAddress((void**)&q,  g_q);
    cudaGetSymbolAddress((void**)&k,  g_k);
    cudaGetSymbolAddress((void**)&v,  g_v);
    cudaGetSymbolAddress((void**)&at, g_at);
    cudaGetSymbolAddress((void**)&x2, g_x2);
    cudaGetSymbolAddress((void**)&ff, g_ff);

    static bool attr_set = false;
    if (!attr_set) {
        cudaFuncSetAttribute(attn_kernel,
                             cudaFuncAttributeMaxDynamicSharedMemorySize,
                             AT_SMEM_BYTES);
        attr_set = true;
    }

    dim3 gDD(Dq / 64, Mq / 128);     // (12, 32)
    dim3 gDF(FFq / 64, Mq / 128);    // (48, 32)

    // LN1
    ln_kernel<<<Mq, 256>>>(x, g1, s1, h);
    // Q, K, V projections
    sgemm_kernel<false, false, false><<<gDD, 256>>>(h, Wq, nullptr, nullptr, q, Mq, Dq, Dq);
    sgemm_kernel<false, false, false><<<gDD, 256>>>(h, Wk, nullptr, nullptr, k, Mq, Dq, Dq);
    sgemm_kernel<false, false, false><<<gDD, 256>>>(h, Wv, nullptr, nullptr, v, Mq, Dq, Dq);
    // flash attention
    {
        dim3 ga(16, Bq * Hq);   // (q tiles, b*h)
        attn_kernel<<<ga, 256, AT_SMEM_BYTES>>>(q, k, v, at);
    }
    // output projection + residual
    sgemm_kernel<false, false, true><<<gDD, 256>>>(at, Wo, nullptr, x, x2, Mq, Dq, Dq);
    // LN2
    ln_kernel<<<Mq, 256>>>(x2, g2, s2, h);
    // MLP up + GELU
    sgemm_kernel<true, true, false><<<gDF, 256>>>(h, W1, b1, nullptr, ff, Mq, FFq, Dq);
    // MLP down + bias + residual -> out
    sgemm_kernel<true, false, true><<<gDD, 256>>>(ff, W2, b2, x2, out, Mq, Dq, FFq);
}

// round 3
// speedup vs baseline: 6.5028x; 1.5994x over previous
#include <cuda_runtime.h>
#include <cuda_bf16.h>
#include <math.h>
#include <stdint.h>

#define Bq 4
#define Sq 1024
#define Dq 768
#define Hq 12
#define HDq 64
#define FFq 3072
#define Mq (Bq*Sq)   // 4096
#define EPSq 1e-5f

// ---------------- scratch (static device globals; no allocation) ----------------
__device__ float g_h [Mq*Dq];
__device__ float g_q [Mq*Dq];
__device__ float g_k [Mq*Dq];
__device__ float g_v [Mq*Dq];
__device__ float g_at[Mq*Dq];
__device__ float g_x2[Mq*Dq];
__device__ float g_ff[Mq*FFq];

// ---------------- LayerNorm: one block per row, D=768 ----------------
__global__ void ln_kernel(const float* __restrict__ x,
                          const float* __restrict__ g,
                          const float* __restrict__ s,
                          float* __restrict__ out) {
    int row = blockIdx.x;
    int t = threadIdx.x;            // 256 threads, 3 elems each
    const float* xr = x + (size_t)row * Dq;
    float v0 = xr[t], v1 = xr[t + 256], v2 = xr[t + 512];
    float lsum = v0 + v1 + v2;
    float lsq  = v0*v0 + v1*v1 + v2*v2;

    __shared__ float rs[64], rq[64];
    for (int o = 16; o > 0; o >>= 1) {
        lsum += __shfl_down_sync(0xffffffff, lsum, o);
        lsq  += __shfl_down_sync(0xffffffff, lsq,  o);
    }
    int warp = t >> 5, lane = t & 31;
    if (lane == 0) { rs[warp] = lsum; rq[warp] = lsq; }
    __syncthreads();
    if (warp == 0) {
        float a = (lane < 8) ? rs[lane] : 0.f;
        float b = (lane < 8) ? rq[lane] : 0.f;
        for (int o = 4; o > 0; o >>= 1) {
            a += __shfl_down_sync(0xffffffff, a, o);
            b += __shfl_down_sync(0xffffffff, b, o);
        }
        if (lane == 0) { rs[0] = a; rq[0] = b; }
    }
    __syncthreads();
    float mean = rs[0] * (1.0f / Dq);
    float var  = rq[0] * (1.0f / Dq) - mean * mean;
    float inv  = rsqrtf(var + EPSq);
    float* orow = out + (size_t)row * Dq;
    orow[t]       = (v0 - mean) * inv * g[t]       + s[t];
    orow[t + 256] = (v1 - mean) * inv * g[t + 256] + s[t + 256];
    orow[t + 512] = (v2 - mean) * inv * g[t + 512] + s[t + 512];
}

// ---------------- tf32 tensor-core GEMM ----------------
// C[M,N] = A[M,K] @ W[N,K]^T, tiles: block 128x128x16, warp 64x32, mma m16n8k8.
// smem layout [row][k] stride GST=20 -> conflict-free fragment loads.
#define GST 20

__device__ __forceinline__ uint32_t f2tf32(float x) {
    uint32_t r;
    asm("cvt.rna.tf32.f32 %0, %1;" : "=r"(r) : "f"(x));
    return r;
}

__device__ __forceinline__ void mma_tf32(float c[4], const uint32_t a[4], const uint32_t b[2]) {
    asm("mma.sync.aligned.m16n8k8.row.col.f32.tf32.tf32.f32 "
        "{%0,%1,%2,%3}, {%4,%5,%6,%7}, {%8,%9}, {%0,%1,%2,%3};"
        : "+f"(c[0]), "+f"(c[1]), "+f"(c[2]), "+f"(c[3])
        : "r"(a[0]), "r"(a[1]), "r"(a[2]), "r"(a[3]), "r"(b[0]), "r"(b[1]));
}

template<bool HAS_BIAS, bool DO_GELU, bool HAS_RES>
__global__ __launch_bounds__(256) void tgemm_kernel(
        const float* __restrict__ A,
        const float* __restrict__ W,
        const float* __restrict__ bias,
        const float* __restrict__ res,
        float* __restrict__ C,
        int M, int N, int K) {
    __shared__ uint32_t As[128 * GST];
    __shared__ uint32_t Bs[128 * GST];

    int tid = threadIdx.x;
    int bm = blockIdx.y, bn = blockIdx.x;
    int warp = tid >> 5, lane = tid & 31;
    int wm = warp >> 2, wn = warp & 3;      // warp grid 2x4 -> warp tile 64x32
    int gid = lane >> 2, tig = lane & 3;

    int lr = tid >> 1, sel = (tid & 1) * 8; // loader: row 0..127, k-half 0/8
    const float* Ap = A + (size_t)(bm * 128 + lr) * K + sel;
    const float* Wp = W + (size_t)(bn * 128 + lr) * K + sel;

    float c[4][4][4];
    #pragma unroll
    for (int i = 0; i < 4; i++)
        #pragma unroll
        for (int j = 0; j < 4; j++)
            #pragma unroll
            for (int f = 0; f < 4; f++) c[i][j][f] = 0.f;

    float4 pa0 = *(const float4*)(Ap);
    float4 pa1 = *(const float4*)(Ap + 4);
    float4 pb0 = *(const float4*)(Wp);
    float4 pb1 = *(const float4*)(Wp + 4);

    for (int k0 = 0; k0 < K; k0 += 16) {
        // stage current tile (convert to tf32 bits)
        uint32_t* as = As + lr * GST + sel;
        as[0] = f2tf32(pa0.x); as[1] = f2tf32(pa0.y); as[2] = f2tf32(pa0.z); as[3] = f2tf32(pa0.w);
        as[4] = f2tf32(pa1.x); as[5] = f2tf32(pa1.y); as[6] = f2tf32(pa1.z); as[7] = f2tf32(pa1.w);
        uint32_t* bs = Bs + lr * GST + sel;
        bs[0] = f2tf32(pb0.x); bs[1] = f2tf32(pb0.y); bs[2] = f2tf32(pb0.z); bs[3] = f2tf32(pb0.w);
        bs[4] = f2tf32(pb1.x); bs[5] = f2tf32(pb1.y); bs[6] = f2tf32(pb1.z); bs[7] = f2tf32(pb1.w);
        __syncthreads();

        if (k0 + 16 < K) {   // prefetch next tile during compute
            pa0 = *(const float4*)(Ap + k0 + 16);
            pa1 = *(const float4*)(Ap + k0 + 20);
            pb0 = *(const float4*)(Wp + k0 + 16);
            pb1 = *(const float4*)(Wp + k0 + 20);
        }

        #pragma unroll
        for (int ks = 0; ks < 2; ks++) {
            int kb = ks * 8;
            uint32_t af[4][4], bf[4][2];
            #pragma unroll
            for (int i = 0; i < 4; i++) {
                int row = wm * 64 + i * 16 + gid;
                af[i][0] = As[row * GST + kb + tig];
                af[i][1] = As[(row + 8) * GST + kb + tig];
                af[i][2] = As[row * GST + kb + tig + 4];
                af[i][3] = As[(row + 8) * GST + kb + tig + 4];
            }
            #pragma unroll
            for (int j = 0; j < 4; j++) {
                int col = wn * 32 + j * 8 + gid;
                bf[j][0] = Bs[col * GST + kb + tig];
                bf[j][1] = Bs[col * GST + kb + tig + 4];
            }
            #pragma unroll
            for (int i = 0; i < 4; i++)
                #pragma unroll
                for (int j = 0; j < 4; j++)
                    mma_tf32(c[i][j], af[i], bf[j]);
        }
        __syncthreads();
    }

    // epilogue
    #pragma unroll
    for (int i = 0; i < 4; i++) {
        #pragma unroll
        for (int j = 0; j < 4; j++) {
            int row0 = bm * 128 + wm * 64 + i * 16 + gid;
            int col0 = bn * 128 + wn * 32 + j * 8 + 2 * tig;
            #pragma unroll
            for (int half = 0; half < 2; half++) {
                int m = row0 + half * 8;
                float v0 = c[i][j][half * 2 + 0];
                float v1 = c[i][j][half * 2 + 1];
                if (HAS_BIAS) { v0 += bias[col0]; v1 += bias[col0 + 1]; }
                if (DO_GELU) {
                    float x3 = v0 * v0 * v0;
                    float tt = tanhf(0.7978845608028654f * (v0 + 0.044715f * x3));
                    v0 = 0.5f * v0 * (1.0f + tt);
                    x3 = v1 * v1 * v1;
                    tt = tanhf(0.7978845608028654f * (v1 + 0.044715f * x3));
                    v1 = 0.5f * v1 * (1.0f + tt);
                }
                if (HAS_RES) {
                    float2 r = *(const float2*)(res + (size_t)m * N + col0);
                    v0 += r.x; v1 += r.y;
                }
                *(float2*)(C + (size_t)m * N + col0) = make_float2(v0, v1);
            }
        }
    }
}

// ---------------- Flash attention: block = (b,h) x 64-row q tile ----------------
#define ATS 68
#define AT_SMEM_BYTES (4 * 64 * ATS * 4)

__global__ void attn_kernel(const float* __restrict__ Q,
                            const float* __restrict__ K,
                            const float* __restrict__ V,
                            float* __restrict__ out) {
    extern __shared__ float sm[];
    float* Qs = sm;                 // [64][ATS]  (row, d), pre-scaled by 1/64
    float* KT = sm + 64 * ATS;      // [64][ATS]  (d, k)
    float* Vs = sm + 2 * 64 * ATS;  // [64][ATS]  (k, d)
    float* Ps = sm + 3 * 64 * ATS;  // [64][ATS]  (row, k)

    int bh = blockIdx.y;            // b*H + h
    int qt = 15 - blockIdx.x;       // heavy tiles first
    int tid = threadIdx.x;          // 256
    int tx = tid & 15, ty = tid >> 4;

    const float* Qp = Q + (size_t)bh * Sq * HDq;
    const float* Kp = K + (size_t)bh * Sq * HDq;
    const float* Vp = V + (size_t)bh * Sq * HDq;

    for (int t = tid; t < 64 * 16; t += 256) {
        int r = t >> 4, c = (t & 15) * 4;
        float4 qv = *(const float4*)(Qp + (size_t)(qt * 64 + r) * HDq + c);
        qv.x *= (1.0f / 64.0f); qv.y *= (1.0f / 64.0f);
        qv.z *= (1.0f / 64.0f); qv.w *= (1.0f / 64.0f);
        *(float4*)(Qs + r * ATS + c) = qv;
    }

    float o[4][4];
    float m_i[4], l_i[4];
    #pragma unroll
    for (int i = 0; i < 4; i++) {
        m_i[i] = -1e30f; l_i[i] = 0.f;
        #pragma unroll
        for (int j = 0; j < 4; j++) o[i][j] = 0.f;
    }

    for (int kt = 0; kt <= qt; kt++) {
        __syncthreads();
        for (int t = tid; t < 1024; t += 256) {
            int k = t & 63, c = (t >> 6) * 4;
            float4 kv = *(const float4*)(Kp + (size_t)(kt * 64 + k) * HDq + c);
            KT[(c + 0) * ATS + k] = kv.x;
            KT[(c + 1) * ATS + k] = kv.y;
            KT[(c + 2) * ATS + k] = kv.z;
            KT[(c + 3) * ATS + k] = kv.w;
            float4 vv = *(const float4*)(Vp + (size_t)(kt * 64 + k) * HDq + c);
            *(float4*)(Vs + k * ATS + c) = vv;
        }
        __syncthreads();

        float s[4][4];
        #pragma unroll
        for (int i = 0; i < 4; i++)
            #pragma unroll
            for (int j = 0; j < 4; j++) s[i][j] = 0.f;
        #pragma unroll 4
        for (int d = 0; d < 64; d++) {
            float4 kv = *(const float4*)(KT + d * ATS + tx * 4);
            float q0 = Qs[(ty * 4 + 0) * ATS + d];
            float q1 = Qs[(ty * 4 + 1) * ATS + d];
            float q2 = Qs[(ty * 4 + 2) * ATS + d];
            float q3 = Qs[(ty * 4 + 3) * ATS + d];
            s[0][0] += q0 * kv.x; s[0][1] += q0 * kv.y; s[0][2] += q0 * kv.z; s[0][3] += q0 * kv.w;
            s[1][0] += q1 * kv.x; s[1][1] += q1 * kv.y; s[1][2] += q1 * kv.z; s[1][3] += q1 * kv.w;
            s[2][0] += q2 * kv.x; s[2][1] += q2 * kv.y; s[2][2] += q2 * kv.z; s[2][3] += q2 * kv.w;
            s[3][0] += q3 * kv.x; s[3][1] += q3 * kv.y; s[3][2] += q3 * kv.z; s[3][3] += q3 * kv.w;
        }

        if (kt == qt) {
            #pragma unroll
            for (int i = 0; i < 4; i++)
                #pragma unroll
                for (int j = 0; j < 4; j++)
                    if (tx * 4 + j > ty * 4 + i) s[i][j] = -1e30f;
        }

        #pragma unroll
        for (int i = 0; i < 4; i++) {
            float mx = fmaxf(fmaxf(s[i][0], s[i][1]), fmaxf(s[i][2], s[i][3]));
            #pragma unroll
            for (int off = 1; off < 16; off <<= 1)
                mx = fmaxf(mx, __shfl_xor_sync(0xffffffff, mx, off));
            float Mnew = fmaxf(m_i[i], mx);
            float alpha = __expf(m_i[i] - Mnew);
            float rs = 0.f;
            #pragma unroll
            for (int j = 0; j < 4; j++) {
                float e = __expf(s[i][j] - Mnew);
                s[i][j] = e;
                rs += e;
            }
            #pragma unroll
            for (int off = 1; off < 16; off <<= 1)
                rs += __shfl_xor_sync(0xffffffff, rs, off);
            l_i[i] = l_i[i] * alpha + rs;
            m_i[i] = Mnew;
            #pragma unroll
            for (int j = 0; j < 4; j++) o[i][j] *= alpha;
        }

        #pragma unroll
        for (int i = 0; i < 4; i++)
            *(float4*)(Ps + (ty * 4 + i) * ATS + tx * 4) =
                make_float4(s[i][0], s[i][1], s[i][2], s[i][3]);
        __syncthreads();

        #pragma unroll 4
        for (int k = 0; k < 64; k++) {
            float4 vv = *(const float4*)(Vs + k * ATS + tx * 4);
            float p0 = Ps[(ty * 4 + 0) * ATS + k];
            float p1 = Ps[(ty * 4 + 1) * ATS + k];
            float p2 = Ps[(ty * 4 + 2) * ATS + k];
            float p3 = Ps[(ty * 4 + 3) * ATS + k];
            o[0][0] += p0 * vv.x; o[0][1] += p0 * vv.y; o[0][2] += p0 * vv.z; o[0][3] += p0 * vv.w;
            o[1][0] += p1 * vv.x; o[1][1] += p1 * vv.y; o[1][2] += p1 * vv.z; o[1][3] += p1 * vv.w;
            o[2][0] += p2 * vv.x; o[2][1] += p2 * vv.y; o[2][2] += p2 * vv.z; o[2][3] += p2 * vv.w;
            o[3][0] += p3 * vv.x; o[3][1] += p3 * vv.y; o[3][2] += p3 * vv.z; o[3][3] += p3 * vv.w;
        }
    }

    int b = bh / Hq, h = bh % Hq;
    #pragma unroll
    for (int i = 0; i < 4; i++) {
        float inv = 1.0f / l_i[i];
        int qrow = qt * 64 + ty * 4 + i;
        float* orow = out + ((size_t)(b * Sq + qrow)) * Dq + h * HDq + tx * 4;
        float4 r = make_float4(o[i][0] * inv, o[i][1] * inv, o[i][2] * inv, o[i][3] * inv);
        *(float4*)orow = r;
    }
}

// ---------------- launch ----------------
extern "C" void kernel_launch(void* const* d_in, const int* in_sizes, int n_in,
                              void* d_out, int out_size) {
    const float* x  = (const float*)d_in[0];
    const float* Wq = (const float*)d_in[1];
    const float* Wk = (const float*)d_in[2];
    const float* Wv = (const float*)d_in[3];
    const float* Wo = (const float*)d_in[4];
    const float* W1 = (const float*)d_in[5];
    const float* b1 = (const float*)d_in[6];
    const float* W2 = (const float*)d_in[7];
    const float* b2 = (const float*)d_in[8];
    const float* g1 = (const float*)d_in[9];
    const float* s1 = (const float*)d_in[10];
    const float* g2 = (const float*)d_in[11];
    const float* s2 = (const float*)d_in[12];
    float* out = (float*)d_out;

    float *h, *q, *k, *v, *at, *x2, *ff;
    cudaGetSymbolAddress((void**)&h,  g_h);
    cudaGetSymbolAddress((void**)&q,  g_q);
    cudaGetSymbolAddress((void**)&k,  g_k);
    cudaGetSymbolAddress((void**)&v,  g_v);
    cudaGetSymbolAddress((void**)&at, g_at);
    cudaGetSymbolAddress((void**)&x2, g_x2);
    cudaGetSymbolAddress((void**)&ff, g_ff);

    static bool attr_set = false;
    if (!attr_set) {
        cudaFuncSetAttribute(attn_kernel,
                             cudaFuncAttributeMaxDynamicSharedMemorySize,
                             AT_SMEM_BYTES);
        attr_set = true;
    }

    dim3 gDD(Dq / 128, Mq / 128);    // (6, 32)
    dim3 gDF(FFq / 128, Mq / 128);   // (24, 32)

    // LN1
    ln_kernel<<<Mq, 256>>>(x, g1, s1, h);
    // Q, K, V projections (tf32 tensor cores)
    tgemm_kernel<false, false, false><<<gDD, 256>>>(h, Wq, nullptr, nullptr, q, Mq, Dq, Dq);
    tgemm_kernel<false, false, false><<<gDD, 256>>>(h, Wk, nullptr, nullptr, k, Mq, Dq, Dq);
    tgemm_kernel<false, false, false><<<gDD, 256>>>(h, Wv, nullptr, nullptr, v, Mq, Dq, Dq);
    // flash attention
    {
        dim3 ga(16, Bq * Hq);
        attn_kernel<<<ga, 256, AT_SMEM_BYTES>>>(q, k, v, at);
    }
    // output projection + residual
    tgemm_kernel<false, false, true><<<gDD, 256>>>(at, Wo, nullptr, x, x2, Mq, Dq, Dq);
    // LN2
    ln_kernel<<<Mq, 256>>>(x2, g2, s2, h);
    // MLP up + GELU
    tgemm_kernel<true, true, false><<<gDF, 256>>>(h, W1, b1, nullptr, ff, Mq, FFq, Dq);
    // MLP down + bias + residual -> out
    tgemm_kernel<true, false, true><<<gDD, 256>>>(ff, W2, b2, x2, out, Mq, Dq, FFq);
}

// round 4
// speedup vs baseline: 7.2911x; 1.1212x over previous
#include <cuda_runtime.h>
#include <cuda_bf16.h>
#include <math.h>
#include <stdint.h>

#define Bq 4
#define Sq 1024
#define Dq 768
#define Hq 12
#define HDq 64
#define FFq 3072
#define Mq (Bq*Sq)   // 4096
#define EPSq 1e-5f

// ---------------- scratch (static device globals; no allocation) ----------------
__device__ float g_h [Mq*Dq];
__device__ float g_q [Mq*Dq];
__device__ float g_k [Mq*Dq];
__device__ float g_v [Mq*Dq];
__device__ float g_at[Mq*Dq];
__device__ float g_x2[Mq*Dq];
__device__ float g_ff[Mq*FFq];

// ---------------- LayerNorm ----------------
__global__ void ln_kernel(const float* __restrict__ x,
                          const float* __restrict__ g,
                          const float* __restrict__ s,
                          float* __restrict__ out) {
    int row = blockIdx.x;
    int t = threadIdx.x;
    const float* xr = x + (size_t)row * Dq;
    float v0 = xr[t], v1 = xr[t + 256], v2 = xr[t + 512];
    float lsum = v0 + v1 + v2;
    float lsq  = v0*v0 + v1*v1 + v2*v2;

    __shared__ float rs[64], rq[64];
    for (int o = 16; o > 0; o >>= 1) {
        lsum += __shfl_down_sync(0xffffffff, lsum, o);
        lsq  += __shfl_down_sync(0xffffffff, lsq,  o);
    }
    int warp = t >> 5, lane = t & 31;
    if (lane == 0) { rs[warp] = lsum; rq[warp] = lsq; }
    __syncthreads();
    if (warp == 0) {
        float a = (lane < 8) ? rs[lane] : 0.f;
        float b = (lane < 8) ? rq[lane] : 0.f;
        for (int o = 4; o > 0; o >>= 1) {
            a += __shfl_down_sync(0xffffffff, a, o);
            b += __shfl_down_sync(0xffffffff, b, o);
        }
        if (lane == 0) { rs[0] = a; rq[0] = b; }
    }
    __syncthreads();
    float mean = rs[0] * (1.0f / Dq);
    float var  = rq[0] * (1.0f / Dq) - mean * mean;
    float inv  = rsqrtf(var + EPSq);
    float* orow = out + (size_t)row * Dq;
    orow[t]       = (v0 - mean) * inv * g[t]       + s[t];
    orow[t + 256] = (v1 - mean) * inv * g[t + 256] + s[t + 256];
    orow[t + 512] = (v2 - mean) * inv * g[t + 512] + s[t + 512];
}

// ---------------- tf32 tensor-core GEMM (double-buffered) ----------------
// C[M,N] = A[M,K] @ W[N,K]^T. Block 128x128x16, warp 64x32, mma m16n8k8.
#define GST 20

__device__ __forceinline__ uint32_t f2tf32(float x) {
    uint32_t r;
    asm("cvt.rna.tf32.f32 %0, %1;" : "=r"(r) : "f"(x));
    return r;
}

__device__ __forceinline__ void mma_tf32(float c[4], const uint32_t a[4], const uint32_t b[2]) {
    asm("mma.sync.aligned.m16n8k8.row.col.f32.tf32.tf32.f32 "
        "{%0,%1,%2,%3}, {%4,%5,%6,%7}, {%8,%9}, {%0,%1,%2,%3};"
        : "+f"(c[0]), "+f"(c[1]), "+f"(c[2]), "+f"(c[3])
        : "r"(a[0]), "r"(a[1]), "r"(a[2]), "r"(a[3]), "r"(b[0]), "r"(b[1]));
}

template<bool HAS_BIAS, bool DO_GELU, bool HAS_RES>
__device__ __forceinline__ void gemm_body(
        const float* __restrict__ A,
        const float* __restrict__ W,
        const float* __restrict__ bias,
        const float* __restrict__ res,
        float* __restrict__ C,
        int M, int N, int K, int bm, int bn,
        uint32_t* As, uint32_t* Bs)   // each [2][128*GST]
{
    int tid = threadIdx.x;
    int warp = tid >> 5, lane = tid & 31;
    int wm = warp >> 2, wn = warp & 3;
    int gid = lane >> 2, tig = lane & 3;

    int lr = tid >> 1, sel = (tid & 1) * 8;
    const float* Ap = A + (size_t)(bm * 128 + lr) * K + sel;
    const float* Wp = W + (size_t)(bn * 128 + lr) * K + sel;

    float c[4][4][4];
    #pragma unroll
    for (int i = 0; i < 4; i++)
        #pragma unroll
        for (int j = 0; j < 4; j++)
            #pragma unroll
            for (int f = 0; f < 4; f++) c[i][j][f] = 0.f;

    // stage tile 0
    {
        float4 a0 = *(const float4*)(Ap);
        float4 a1 = *(const float4*)(Ap + 4);
        float4 b0 = *(const float4*)(Wp);
        float4 b1 = *(const float4*)(Wp + 4);
        uint32_t* as = As + lr * GST + sel;
        as[0] = f2tf32(a0.x); as[1] = f2tf32(a0.y); as[2] = f2tf32(a0.z); as[3] = f2tf32(a0.w);
        as[4] = f2tf32(a1.x); as[5] = f2tf32(a1.y); as[6] = f2tf32(a1.z); as[7] = f2tf32(a1.w);
        uint32_t* bs = Bs + lr * GST + sel;
        bs[0] = f2tf32(b0.x); bs[1] = f2tf32(b0.y); bs[2] = f2tf32(b0.z); bs[3] = f2tf32(b0.w);
        bs[4] = f2tf32(b1.x); bs[5] = f2tf32(b1.y); bs[6] = f2tf32(b1.z); bs[7] = f2tf32(b1.w);
    }
    __syncthreads();

    int buf = 0;
    const int BUFO = 128 * GST;

    for (int k0 = 0; k0 < K; k0 += 16) {
        float4 a0, a1, b0, b1;
        bool more = (k0 + 16) < K;
        if (more) {
            a0 = *(const float4*)(Ap + k0 + 16);
            a1 = *(const float4*)(Ap + k0 + 20);
            b0 = *(const float4*)(Wp + k0 + 16);
            b1 = *(const float4*)(Wp + k0 + 20);
        }

        const uint32_t* Ab = As + buf * BUFO;
        const uint32_t* Bb = Bs + buf * BUFO;
        #pragma unroll
        for (int ks = 0; ks < 2; ks++) {
            int kb = ks * 8;
            uint32_t af[4][4], bf[4][2];
            #pragma unroll
            for (int i = 0; i < 4; i++) {
                int row = wm * 64 + i * 16 + gid;
                af[i][0] = Ab[row * GST + kb + tig];
                af[i][1] = Ab[(row + 8) * GST + kb + tig];
                af[i][2] = Ab[row * GST + kb + tig + 4];
                af[i][3] = Ab[(row + 8) * GST + kb + tig + 4];
            }
            #pragma unroll
            for (int j = 0; j < 4; j++) {
                int col = wn * 32 + j * 8 + gid;
                bf[j][0] = Bb[col * GST + kb + tig];
                bf[j][1] = Bb[col * GST + kb + tig + 4];
            }
            #pragma unroll
            for (int i = 0; i < 4; i++)
                #pragma unroll
                for (int j = 0; j < 4; j++)
                    mma_tf32(c[i][j], af[i], bf[j]);
        }

        if (more) {
            uint32_t* as = As + (buf ^ 1) * BUFO + lr * GST + sel;
            as[0] = f2tf32(a0.x); as[1] = f2tf32(a0.y); as[2] = f2tf32(a0.z); as[3] = f2tf32(a0.w);
            as[4] = f2tf32(a1.x); as[5] = f2tf32(a1.y); as[6] = f2tf32(a1.z); as[7] = f2tf32(a1.w);
            uint32_t* bs = Bs + (buf ^ 1) * BUFO + lr * GST + sel;
            bs[0] = f2tf32(b0.x); bs[1] = f2tf32(b0.y); bs[2] = f2tf32(b0.z); bs[3] = f2tf32(b0.w);
            bs[4] = f2tf32(b1.x); bs[5] = f2tf32(b1.y); bs[6] = f2tf32(b1.z); bs[7] = f2tf32(b1.w);
            __syncthreads();
            buf ^= 1;
        }
    }

    // epilogue
    #pragma unroll
    for (int i = 0; i < 4; i++) {
        #pragma unroll
        for (int j = 0; j < 4; j++) {
            int row0 = bm * 128 + wm * 64 + i * 16 + gid;
            int col0 = bn * 128 + wn * 32 + j * 8 + 2 * tig;
            #pragma unroll
            for (int half = 0; half < 2; half++) {
                int m = row0 + half * 8;
                float v0 = c[i][j][half * 2 + 0];
                float v1 = c[i][j][half * 2 + 1];
                if (HAS_BIAS) { v0 += bias[col0]; v1 += bias[col0 + 1]; }
                if (DO_GELU) {
                    float x3 = v0 * v0 * v0;
                    float tt = tanhf(0.7978845608028654f * (v0 + 0.044715f * x3));
                    v0 = 0.5f * v0 * (1.0f + tt);
                    x3 = v1 * v1 * v1;
                    tt = tanhf(0.7978845608028654f * (v1 + 0.044715f * x3));
                    v1 = 0.5f * v1 * (1.0f + tt);
                }
                if (HAS_RES) {
                    float2 r = *(const float2*)(res + (size_t)m * N + col0);
                    v0 += r.x; v1 += r.y;
                }
                *(float2*)(C + (size_t)m * N + col0) = make_float2(v0, v1);
            }
        }
    }
}

template<bool HAS_BIAS, bool DO_GELU, bool HAS_RES>
__global__ __launch_bounds__(256, 2) void tgemm_kernel(
        const float* __restrict__ A,
        const float* __restrict__ W,
        const float* __restrict__ bias,
        const float* __restrict__ res,
        float* __restrict__ C,
        int M, int N, int K) {
    __shared__ uint32_t As[2 * 128 * GST];
    __shared__ uint32_t Bs[2 * 128 * GST];
    gemm_body<HAS_BIAS, DO_GELU, HAS_RES>(A, W, bias, res, C, M, N, K,
                                          blockIdx.y, blockIdx.x, As, Bs);
}

// fused QKV: blockIdx.z selects weight / output
__global__ __launch_bounds__(256, 2) void qkv_kernel(
        const float* __restrict__ A,
        const float* __restrict__ Wqp,
        const float* __restrict__ Wkp,
        const float* __restrict__ Wvp,
        float* __restrict__ Qo,
        float* __restrict__ Ko,
        float* __restrict__ Vo) {
    __shared__ uint32_t As[2 * 128 * GST];
    __shared__ uint32_t Bs[2 * 128 * GST];
    const float* W = (blockIdx.z == 0) ? Wqp : (blockIdx.z == 1) ? Wkp : Wvp;
    float* C = (blockIdx.z == 0) ? Qo : (blockIdx.z == 1) ? Ko : Vo;
    gemm_body<false, false, false>(A, W, nullptr, nullptr, C, Mq, Dq, Dq,
                                   blockIdx.y, blockIdx.x, As, Bs);
}

// ---------------- Flash attention: block = (b,h) x 64-row q tile ----------------
#define ATS 68
#define AT_SMEM_BYTES (4 * 64 * ATS * 4)

__global__ void attn_kernel(const float* __restrict__ Q,
                            const float* __restrict__ K,
                            const float* __restrict__ V,
                            float* __restrict__ out) {
    extern __shared__ float sm[];
    float* Qs = sm;
    float* KT = sm + 64 * ATS;
    float* Vs = sm + 2 * 64 * ATS;
    float* Ps = sm + 3 * 64 * ATS;

    int bh = blockIdx.y;
    int qt = 15 - blockIdx.x;
    int tid = threadIdx.x;
    int tx = tid & 15, ty = tid >> 4;

    const float* Qp = Q + (size_t)bh * Sq * HDq;
    const float* Kp = K + (size_t)bh * Sq * HDq;
    const float* Vp = V + (size_t)bh * Sq * HDq;

    for (int t = tid; t < 64 * 16; t += 256) {
        int r = t >> 4, c = (t & 15) * 4;
        float4 qv = *(const float4*)(Qp + (size_t)(qt * 64 + r) * HDq + c);
        qv.x *= (1.0f / 64.0f); qv.y *= (1.0f / 64.0f);
        qv.z *= (1.0f / 64.0f); qv.w *= (1.0f / 64.0f);
        *(float4*)(Qs + r * ATS + c) = qv;
    }

    float o[4][4];
    float m_i[4], l_i[4];
    #pragma unroll
    for (int i = 0; i < 4; i++) {
        m_i[i] = -1e30f; l_i[i] = 0.f;
        #pragma unroll
        for (int j = 0; j < 4; j++) o[i][j] = 0.f;
    }

    for (int kt = 0; kt <= qt; kt++) {
        __syncthreads();
        for (int t = tid; t < 1024; t += 256) {
            int k = t & 63, c = (t >> 6) * 4;
            float4 kv = *(const float4*)(Kp + (size_t)(kt * 64 + k) * HDq + c);
            KT[(c + 0) * ATS + k] = kv.x;
            KT[(c + 1) * ATS + k] = kv.y;
            KT[(c + 2) * ATS + k] = kv.z;
            KT[(c + 3) * ATS + k] = kv.w;
            float4 vv = *(const float4*)(Vp + (size_t)(kt * 64 + k) * HDq + c);
            *(float4*)(Vs + k * ATS + c) = vv;
        }
        __syncthreads();

        float s[4][4];
        #pragma unroll
        for (int i = 0; i < 4; i++)
            #pragma unroll
            for (int j = 0; j < 4; j++) s[i][j] = 0.f;
        #pragma unroll 4
        for (int d = 0; d < 64; d++) {
            float4 kv = *(const float4*)(KT + d * ATS + tx * 4);
            float q0 = Qs[(ty * 4 + 0) * ATS + d];
            float q1 = Qs[(ty * 4 + 1) * ATS + d];
            float q2 = Qs[(ty * 4 + 2) * ATS + d];
            float q3 = Qs[(ty * 4 + 3) * ATS + d];
            s[0][0] += q0 * kv.x; s[0][1] += q0 * kv.y; s[0][2] += q0 * kv.z; s[0][3] += q0 * kv.w;
            s[1][0] += q1 * kv.x; s[1][1] += q1 * kv.y; s[1][2] += q1 * kv.z; s[1][3] += q1 * kv.w;
            s[2][0] += q2 * kv.x; s[2][1] += q2 * kv.y; s[2][2] += q2 * kv.z; s[2][3] += q2 * kv.w;
            s[3][0] += q3 * kv.x; s[3][1] += q3 * kv.y; s[3][2] += q3 * kv.z; s[3][3] += q3 * kv.w;
        }

        if (kt == qt) {
            #pragma unroll
            for (int i = 0; i < 4; i++)
                #pragma unroll
                for (int j = 0; j < 4; j++)
                    if (tx * 4 + j > ty * 4 + i) s[i][j] = -1e30f;
        }

        #pragma unroll
        for (int i = 0; i < 4; i++) {
            float mx = fmaxf(fmaxf(s[i][0], s[i][1]), fmaxf(s[i][2], s[i][3]));
            #pragma unroll
            for (int off = 1; off < 16; off <<= 1)
                mx = fmaxf(mx, __shfl_xor_sync(0xffffffff, mx, off));
            float Mnew = fmaxf(m_i[i], mx);
            float alpha = __expf(m_i[i] - Mnew);
            float rs = 0.f;
            #pragma unroll
            for (int j = 0; j < 4; j++) {
                float e = __expf(s[i][j] - Mnew);
                s[i][j] = e;
                rs += e;
            }
            #pragma unroll
            for (int off = 1; off < 16; off <<= 1)
                rs += __shfl_xor_sync(0xffffffff, rs, off);
            l_i[i] = l_i[i] * alpha + rs;
            m_i[i] = Mnew;
            #pragma unroll
            for (int j = 0; j < 4; j++) o[i][j] *= alpha;
        }

        #pragma unroll
        for (int i = 0; i < 4; i++)
            *(float4*)(Ps + (ty * 4 + i) * ATS + tx * 4) =
                make_float4(s[i][0], s[i][1], s[i][2], s[i][3]);
        __syncthreads();

        #pragma unroll 4
        for (int k = 0; k < 64; k++) {
            float4 vv = *(const float4*)(Vs + k * ATS + tx * 4);
            float p0 = Ps[(ty * 4 + 0) * ATS + k];
            float p1 = Ps[(ty * 4 + 1) * ATS + k];
            float p2 = Ps[(ty * 4 + 2) * ATS + k];
            float p3 = Ps[(ty * 4 + 3) * ATS + k];
            o[0][0] += p0 * vv.x; o[0][1] += p0 * vv.y; o[0][2] += p0 * vv.z; o[0][3] += p0 * vv.w;
            o[1][0] += p1 * vv.x; o[1][1] += p1 * vv.y; o[1][2] += p1 * vv.z; o[1][3] += p1 * vv.w;
            o[2][0] += p2 * vv.x; o[2][1] += p2 * vv.y; o[2][2] += p2 * vv.z; o[2][3] += p2 * vv.w;
            o[3][0] += p3 * vv.x; o[3][1] += p3 * vv.y; o[3][2] += p3 * vv.z; o[3][3] += p3 * vv.w;
        }
    }

    int b = bh / Hq, h = bh % Hq;
    #pragma unroll
    for (int i = 0; i < 4; i++) {
        float inv = 1.0f / l_i[i];
        int qrow = qt * 64 + ty * 4 + i;
        float* orow = out + ((size_t)(b * Sq + qrow)) * Dq + h * HDq + tx * 4;
        float4 r = make_float4(o[i][0] * inv, o[i][1] * inv, o[i][2] * inv, o[i][3] * inv);
        *(float4*)orow = r;
    }
}

// ---------------- launch ----------------
extern "C" void kernel_launch(void* const* d_in, const int* in_sizes, int n_in,
                              void* d_out, int out_size) {
    const float* x  = (const float*)d_in[0];
    const float* Wq = (const float*)d_in[1];
    const float* Wk = (const float*)d_in[2];
    const float* Wv = (const float*)d_in[3];
    const float* Wo = (const float*)d_in[4];
    const float* W1 = (const float*)d_in[5];
    const float* b1 = (const float*)d_in[6];
    const float* W2 = (const float*)d_in[7];
    const float* b2 = (const float*)d_in[8];
    const float* g1 = (const float*)d_in[9];
    const float* s1 = (const float*)d_in[10];
    const float* g2 = (const float*)d_in[11];
    const float* s2 = (const float*)d_in[12];
    float* out = (float*)d_out;

    float *h, *q, *k, *v, *at, *x2, *ff;
    cudaGetSymbolAddress((void**)&h,  g_h);
    cudaGetSymbolAddress((void**)&q,  g_q);
    cudaGetSymbolAddress((void**)&k,  g_k);
    cudaGetSymbolAddress((void**)&v,  g_v);
    cudaGetSymbolAddress((void**)&at, g_at);
    cudaGetSymbolAddress((void**)&x2, g_x2);
    cudaGetSymbolAddress((void**)&ff, g_ff);

    static bool attr_set = false;
    if (!attr_set) {
        cudaFuncSetAttribute(attn_kernel,
                             cudaFuncAttributeMaxDynamicSharedMemorySize,
                             AT_SMEM_BYTES);
        attr_set = true;
    }

    dim3 gDD(Dq / 128, Mq / 128);        // (6, 32)
    dim3 gQKV(Dq / 128, Mq / 128, 3);    // (6, 32, 3) = 576 blocks
    dim3 gDF(FFq / 128, Mq / 128);       // (24, 32)

    // LN1
    ln_kernel<<<Mq, 256>>>(x, g1, s1, h);
    // fused Q,K,V projections
    qkv_kernel<<<gQKV, 256>>>(h, Wq, Wk, Wv, q, k, v);
    // flash attention
    {
        dim3 ga(16, Bq * Hq);
        attn_kernel<<<ga, 256, AT_SMEM_BYTES>>>(q, k, v, at);
    }
    // output projection + residual
    tgemm_kernel<false, false, true><<<gDD, 256>>>(at, Wo, nullptr, x, x2, Mq, Dq, Dq);
    // LN2
    ln_kernel<<<Mq, 256>>>(x2, g2, s2, h);
    // MLP up + GELU
    tgemm_kernel<true, true, false><<<gDF, 256>>>(h, W1, b1, nullptr, ff, Mq, FFq, Dq);
    // MLP down + bias + residual -> out
    tgemm_kernel<true, false, true><<<gDD, 256>>>(ff, W2, b2, x2, out, Mq, Dq, FFq);
}